// round 5
// baseline (speedup 1.0000x reference)
#include <cuda_runtime.h>
#include <math.h>

namespace {

constexpr int B  = 64;
constexpr int T  = 256;
constexpr int IN = 512;
constexpr int H  = 1024;
constexpr int M  = B * T;   // 16384

typedef unsigned long long u64;

// Scratch (device globals — no allocation allowed)
__device__ float g_P[3][(size_t)M * H];   // masked input projections + bias: [f, o, c]
__device__ float g_h[2][B * H];           // h ping-pong
__device__ float g_c[B * H];              // cell state

__device__ __forceinline__ u64 pack2(float v) {
    u64 r; asm("mov.b64 %0, {%1, %2};" : "=l"(r) : "f"(v), "f"(v)); return r;
}
__device__ __forceinline__ u64 fma2(u64 a, u64 b, u64 c) {
    u64 d; asm("fma.rn.f32x2 %0, %1, %2, %3;" : "=l"(d) : "l"(a), "l"(b), "l"(c)); return d;
}
__device__ __forceinline__ float2 unpack2(u64 v) {
    float2 f; asm("mov.b64 {%0, %1}, %2;" : "=f"(f.x), "=f"(f.y) : "l"(v)); return f;
}
__device__ __forceinline__ float sigmoidf_(float x) { return 1.0f / (1.0f + expf(-x)); }

// ---------------------------------------------------------------------------
// init: zero h0, c0
// ---------------------------------------------------------------------------
__global__ void init_state() {
    int i = blockIdx.x * blockDim.x + threadIdx.x;
    if (i < B * H) { g_h[0][i] = 0.0f; g_c[i] = 0.0f; }
}

// ---------------------------------------------------------------------------
// Input projection: for gate g in {f,o,c}:
//   P_g[m][n] = sigmoid(X[m]·Wm_g[n]) * (X[m]·W_g[n]) + b_g[n]
// GEMM M=16384, N=1024, K=512, two B-matrices per output.
// Tile 64x64x16, 128 threads, thread tile TM=8 (4 f32x2 m-pairs) x TN=4.
// ---------------------------------------------------------------------------
constexpr int BM = 64, BN = 64, BK = 16;

__global__ __launch_bounds__(128)
void input_proj(const float* __restrict__ X,
                const float* __restrict__ W0, const float* __restrict__ Wm0, const float* __restrict__ b0,
                const float* __restrict__ W1, const float* __restrict__ Wm1, const float* __restrict__ b1,
                const float* __restrict__ W2, const float* __restrict__ Wm2, const float* __restrict__ b2)
{
    __shared__ __align__(16) float sX[BK][BM + 2];
    __shared__ __align__(16) float sW[BK][BN + 2];
    __shared__ __align__(16) float sM[BK][BN + 2];

    const int g = blockIdx.z;
    const float* Wg  = (g == 0) ? W0  : (g == 1) ? W1  : W2;
    const float* Wmg = (g == 0) ? Wm0 : (g == 1) ? Wm1 : Wm2;
    const float* bg  = (g == 0) ? b0  : (g == 1) ? b1  : b2;

    const int tid = threadIdx.x;
    const int tx = tid & 15;    // n-group: n = tx*4 + j
    const int ty = tid >> 4;    // m-group: m = ty*8 + ...
    const int m_blk = blockIdx.y * BM;
    const int n_blk = blockIdx.x * BN;

    const float* Xb = X   + (size_t)m_blk * IN;
    const float* Wb = Wg  + (size_t)n_blk * IN;
    const float* Mb = Wmg + (size_t)n_blk * IN;

    u64 accW[4][4], accM[4][4];
    #pragma unroll
    for (int j = 0; j < 4; j++)
        #pragma unroll
        for (int i = 0; i < 4; i++) { accW[j][i] = 0ull; accM[j][i] = 0ull; }

    // register prefetch buffers (double-buffer global->reg->smem)
    float4 xb[2], wb[2], mb[2];
    #pragma unroll
    for (int r = 0; r < 2; r++) {
        int idx = tid + r * 128;
        int row = idx >> 2, k4 = (idx & 3) << 2;
        size_t off = (size_t)row * IN + k4;
        xb[r] = *(const float4*)(Xb + off);
        wb[r] = *(const float4*)(Wb + off);
        mb[r] = *(const float4*)(Mb + off);
    }

    for (int k0 = 0; k0 < IN; k0 += BK) {
        #pragma unroll
        for (int r = 0; r < 2; r++) {
            int idx = tid + r * 128;
            int row = idx >> 2, k4 = (idx & 3) << 2;
            sX[k4 + 0][row] = xb[r].x; sX[k4 + 1][row] = xb[r].y;
            sX[k4 + 2][row] = xb[r].z; sX[k4 + 3][row] = xb[r].w;
            sW[k4 + 0][row] = wb[r].x; sW[k4 + 1][row] = wb[r].y;
            sW[k4 + 2][row] = wb[r].z; sW[k4 + 3][row] = wb[r].w;
            sM[k4 + 0][row] = mb[r].x; sM[k4 + 1][row] = mb[r].y;
            sM[k4 + 2][row] = mb[r].z; sM[k4 + 3][row] = mb[r].w;
        }
        __syncthreads();

        if (k0 + BK < IN) {
            #pragma unroll
            for (int r = 0; r < 2; r++) {
                int idx = tid + r * 128;
                int row = idx >> 2, k4 = (idx & 3) << 2;
                size_t off = (size_t)row * IN + (k0 + BK) + k4;
                xb[r] = *(const float4*)(Xb + off);
                wb[r] = *(const float4*)(Wb + off);
                mb[r] = *(const float4*)(Mb + off);
            }
        }

        #pragma unroll
        for (int kk = 0; kk < BK; kk++) {
            u64 a[4];
            #pragma unroll
            for (int i = 0; i < 4; i++)
                a[i] = *(const u64*)&sX[kk][ty * 8 + 2 * i];
            #pragma unroll
            for (int j = 0; j < 4; j++) {
                u64 w2 = pack2(sW[kk][tx * 4 + j]);
                u64 m2 = pack2(sM[kk][tx * 4 + j]);
                #pragma unroll
                for (int i = 0; i < 4; i++) {
                    accW[j][i] = fma2(a[i], w2, accW[j][i]);
                    accM[j][i] = fma2(a[i], m2, accM[j][i]);
                }
            }
        }
        __syncthreads();
    }

    float bv[4];
    #pragma unroll
    for (int j = 0; j < 4; j++) bv[j] = bg[n_blk + tx * 4 + j];

    float* P = g_P[g];
    #pragma unroll
    for (int i = 0; i < 4; i++) {
        float2 w[4], mm[4];
        #pragma unroll
        for (int j = 0; j < 4; j++) { w[j] = unpack2(accW[j][i]); mm[j] = unpack2(accM[j][i]); }
        const int m = m_blk + ty * 8 + 2 * i;
        float4 v0, v1;
        v0.x = sigmoidf_(mm[0].x) * w[0].x + bv[0];
        v0.y = sigmoidf_(mm[1].x) * w[1].x + bv[1];
        v0.z = sigmoidf_(mm[2].x) * w[2].x + bv[2];
        v0.w = sigmoidf_(mm[3].x) * w[3].x + bv[3];
        v1.x = sigmoidf_(mm[0].y) * w[0].y + bv[0];
        v1.y = sigmoidf_(mm[1].y) * w[1].y + bv[1];
        v1.z = sigmoidf_(mm[2].y) * w[2].y + bv[2];
        v1.w = sigmoidf_(mm[3].y) * w[3].y + bv[3];
        *(float4*)&P[(size_t)m * H + n_blk + tx * 4]       = v0;
        *(float4*)&P[(size_t)(m + 1) * H + n_blk + tx * 4] = v1;
    }
}

// ---------------------------------------------------------------------------
// Recurrent step (fused): for gate g: R_g = sigmoid(h·Um_g)*(h·U_g);
//   f = sig(P_f + R_f); o = sig(P_o + R_o); c = f*c + tanh(P_c + R_c); h = o*c
// GEMM M=64(=B), N=1024, K=1024, 6 weight matrices fused into one block's
// accumulators so the LSTM cell update is a local epilogue.
// Grid = 128 blocks (BN=8), 128 threads, TM=4 (2 f32x2 m-pairs) x TN=1 x 6 mats.
// ---------------------------------------------------------------------------
constexpr int RBN = 8, RBK = 32;

__global__ __launch_bounds__(128)
void lstm_step(int t,
               const float* __restrict__ Uf, const float* __restrict__ Umf,
               const float* __restrict__ Uo, const float* __restrict__ Umo,
               const float* __restrict__ Uc, const float* __restrict__ Umc,
               float* __restrict__ out)
{
    __shared__ __align__(16) float sH[RBK][B + 2];
    __shared__ __align__(16) float sU[6][RBK][RBN];

    const int tid = threadIdx.x;
    const int tx = tid & 7;     // n within tile
    const int ty = tid >> 3;    // m-group (0..15), m0 = ty*4
    const int n_blk = blockIdx.x * RBN;
    const float* __restrict__ hprev = g_h[t & 1];
    float* __restrict__ hnext = g_h[(t + 1) & 1];

    u64 acc[6][2];
    #pragma unroll
    for (int mat = 0; mat < 6; mat++) { acc[mat][0] = 0ull; acc[mat][1] = 0ull; }

    // loader decomposition
    const int lk4 = (tid & 7) << 2;         // k offset within chunk (float4 granularity)
    const int lhm = tid >> 3;               // base m row for h loader (0..15), +16*r
    const int lun = (tid >> 3) & 7;         // n row for U loader

    // per-thread advancing U pointers (3 mats per thread across r=0..2)
    const float* uptr[3];
    #pragma unroll
    for (int r = 0; r < 3; r++) {
        int mat = (tid >> 6) + 2 * r;       // tid>>6 in {0,1}
        const float* up = (mat == 0) ? Uf : (mat == 1) ? Umf : (mat == 2) ? Uo :
                          (mat == 3) ? Umo : (mat == 4) ? Uc : Umc;
        uptr[r] = up + (size_t)(n_blk + lun) * H + lk4;
    }
    const size_t hbase = (size_t)lhm * H + lk4;

    float4 hb[4], ub[3];
    #pragma unroll
    for (int r = 0; r < 4; r++) hb[r] = *(const float4*)(hprev + hbase + (size_t)16 * r * H);
    #pragma unroll
    for (int r = 0; r < 3; r++) ub[r] = *(const float4*)(uptr[r]);

    for (int k0 = 0; k0 < H; k0 += RBK) {
        #pragma unroll
        for (int r = 0; r < 4; r++) {
            int m = lhm + 16 * r;
            sH[lk4 + 0][m] = hb[r].x; sH[lk4 + 1][m] = hb[r].y;
            sH[lk4 + 2][m] = hb[r].z; sH[lk4 + 3][m] = hb[r].w;
        }
        #pragma unroll
        for (int r = 0; r < 3; r++) {
            int mat = (tid >> 6) + 2 * r;
            sU[mat][lk4 + 0][lun] = ub[r].x; sU[mat][lk4 + 1][lun] = ub[r].y;
            sU[mat][lk4 + 2][lun] = ub[r].z; sU[mat][lk4 + 3][lun] = ub[r].w;
        }
        __syncthreads();

        if (k0 + RBK < H) {
            #pragma unroll
            for (int r = 0; r < 4; r++)
                hb[r] = *(const float4*)(hprev + hbase + (size_t)(k0 + RBK) + (size_t)16 * r * H);
            #pragma unroll
            for (int r = 0; r < 3; r++) { uptr[r] += RBK; ub[r] = *(const float4*)(uptr[r]); }
        }

        #pragma unroll
        for (int kk = 0; kk < RBK; kk++) {
            u64 a0 = *(const u64*)&sH[kk][ty * 4];
            u64 a1 = *(const u64*)&sH[kk][ty * 4 + 2];
            #pragma unroll
            for (int mat = 0; mat < 6; mat++) {
                u64 w2 = pack2(sU[mat][kk][tx]);
                acc[mat][0] = fma2(a0, w2, acc[mat][0]);
                acc[mat][1] = fma2(a1, w2, acc[mat][1]);
            }
        }
        __syncthreads();
    }

    // fused LSTM cell epilogue
    const int n = n_blk + tx;
    #pragma unroll
    for (int p = 0; p < 2; p++) {
        float2 df  = unpack2(acc[0][p]);
        float2 dfm = unpack2(acc[1][p]);
        float2 do2 = unpack2(acc[2][p]);
        float2 dom = unpack2(acc[3][p]);
        float2 dc  = unpack2(acc[4][p]);
        float2 dcm = unpack2(acc[5][p]);
        #pragma unroll
        for (int hh = 0; hh < 2; hh++) {
            int b = ty * 4 + p * 2 + hh;
            float rf = sigmoidf_(hh ? dfm.y : dfm.x) * (hh ? df.y  : df.x);
            float ro = sigmoidf_(hh ? dom.y : dom.x) * (hh ? do2.y : do2.x);
            float rc = sigmoidf_(hh ? dcm.y : dcm.x) * (hh ? dc.y  : dc.x);
            size_t pidx = ((size_t)(b * T + t)) * H + n;
            float f = sigmoidf_(g_P[0][pidx] + rf);
            float o = sigmoidf_(g_P[1][pidx] + ro);
            float cn = f * g_c[b * H + n] + tanhf(g_P[2][pidx] + rc);
            g_c[b * H + n] = cn;
            float hn = o * cn;
            hnext[b * H + n] = hn;
            out[pidx] = hn;
        }
    }
}

// ---------------------------------------------------------------------------
// Tail: final states hT, cT appended after output [B,T,H]
// ---------------------------------------------------------------------------
__global__ void tail_copy(float* __restrict__ out) {
    int i = blockIdx.x * blockDim.x + threadIdx.x;
    if (i < B * H) {
        out[(size_t)M * H + i]         = g_h[0][i];   // T even -> final h in buffer 0
        out[(size_t)M * H + B * H + i] = g_c[i];
    }
}

} // anonymous namespace

extern "C" void kernel_launch(void* const* d_in, const int* in_sizes, int n_in,
                              void* d_out, int out_size) {
    (void)in_sizes; (void)n_in;
    const float* X    = (const float*)d_in[0];
    const float* W_f  = (const float*)d_in[1];
    const float* Wm_f = (const float*)d_in[2];
    const float* U_f  = (const float*)d_in[3];
    const float* Um_f = (const float*)d_in[4];
    const float* b_f  = (const float*)d_in[5];
    // inputs 6..10 are the i-gate: computed but unused by the reference -> skipped
    const float* W_o  = (const float*)d_in[11];
    const float* Wm_o = (const float*)d_in[12];
    const float* U_o  = (const float*)d_in[13];
    const float* Um_o = (const float*)d_in[14];
    const float* b_o  = (const float*)d_in[15];
    const float* W_c  = (const float*)d_in[16];
    const float* Wm_c = (const float*)d_in[17];
    const float* U_c  = (const float*)d_in[18];
    const float* Um_c = (const float*)d_in[19];
    const float* b_c  = (const float*)d_in[20];
    float* out = (float*)d_out;

    init_state<<<(B * H + 255) / 256, 256>>>();

    dim3 pg(H / BN, M / BM, 3);
    input_proj<<<pg, 128>>>(X, W_f, Wm_f, b_f, W_o, Wm_o, b_o, W_c, Wm_c, b_c);

    for (int t = 0; t < T; t++)
        lstm_step<<<H / RBN, 128>>>(t, U_f, Um_f, U_o, Um_o, U_c, Um_c, out);

    if (out_size >= M * H + 2 * B * H)
        tail_copy<<<(B * H + 255) / 256, 256>>>(out);
}

// round 6
// speedup vs baseline: 1.5785x; 1.5785x over previous
#include <cuda_runtime.h>
#include <math.h>

namespace {

constexpr int B  = 64;
constexpr int T  = 256;
constexpr int IN = 512;
constexpr int H  = 1024;
constexpr int M  = B * T;   // 16384

constexpr int RGRID = 128;  // persistent blocks, each owns 8 N-columns
constexpr int RTHREADS = 256;

typedef unsigned long long u64;

// Scratch (device globals — no allocation allowed)
__device__ float g_P[3][(size_t)M * H];   // masked input projections + bias: [f, o, c]
__device__ float g_h[2][B * H];           // h ping-pong

// grid barrier state
__device__ unsigned g_bar_count = 0;
__device__ volatile unsigned g_bar_gen = 0;

__device__ __forceinline__ u64 pack2(float v) {
    u64 r; asm("mov.b64 %0, {%1, %2};" : "=l"(r) : "f"(v), "f"(v)); return r;
}
__device__ __forceinline__ u64 fma2(u64 a, u64 b, u64 c) {
    u64 d; asm("fma.rn.f32x2 %0, %1, %2, %3;" : "=l"(d) : "l"(a), "l"(b), "l"(c)); return d;
}
__device__ __forceinline__ float2 unpack2(u64 v) {
    float2 f; asm("mov.b64 {%0, %1}, %2;" : "=f"(f.x), "=f"(f.y) : "l"(v)); return f;
}
__device__ __forceinline__ float sigmoidf_(float x) { return 1.0f / (1.0f + expf(-x)); }

__device__ __forceinline__ float4 ldcg4(const float* p) {
    float4 v;
    asm volatile("ld.global.cg.v4.f32 {%0,%1,%2,%3}, [%4];"
                 : "=f"(v.x), "=f"(v.y), "=f"(v.z), "=f"(v.w) : "l"(p));
    return v;
}

// All blocks are co-resident (1 block/SM via smem footprint, grid 128 <= 148 SMs).
__device__ __forceinline__ void grid_barrier() {
    __syncthreads();
    if (threadIdx.x == 0) {
        __threadfence();
        unsigned old = g_bar_gen;
        if (atomicAdd(&g_bar_count, 1u) == (unsigned)(gridDim.x - 1)) {
            g_bar_count = 0;
            __threadfence();
            g_bar_gen = old + 1;
        } else {
            while (g_bar_gen == old) { }
        }
        __threadfence();
    }
    __syncthreads();
}

// ---------------------------------------------------------------------------
// Input projection: for gate g in {f,o,c}:
//   P_g[m][n] = sigmoid(X[m]·Wm_g[n]) * (X[m]·W_g[n]) + b_g[n]
// GEMM M=16384, N=1024, K=512, two B-matrices per output.
// ---------------------------------------------------------------------------
constexpr int BM = 64, BN = 64, BK = 16;

__global__ __launch_bounds__(128)
void input_proj(const float* __restrict__ X,
                const float* __restrict__ W0, const float* __restrict__ Wm0, const float* __restrict__ b0,
                const float* __restrict__ W1, const float* __restrict__ Wm1, const float* __restrict__ b1,
                const float* __restrict__ W2, const float* __restrict__ Wm2, const float* __restrict__ b2)
{
    __shared__ __align__(16) float sX[BK][BM + 2];
    __shared__ __align__(16) float sW[BK][BN + 2];
    __shared__ __align__(16) float sM[BK][BN + 2];

    const int g = blockIdx.z;
    const float* Wg  = (g == 0) ? W0  : (g == 1) ? W1  : W2;
    const float* Wmg = (g == 0) ? Wm0 : (g == 1) ? Wm1 : Wm2;
    const float* bg  = (g == 0) ? b0  : (g == 1) ? b1  : b2;

    const int tid = threadIdx.x;
    const int tx = tid & 15;
    const int ty = tid >> 4;
    const int m_blk = blockIdx.y * BM;
    const int n_blk = blockIdx.x * BN;

    const float* Xb = X   + (size_t)m_blk * IN;
    const float* Wb = Wg  + (size_t)n_blk * IN;
    const float* Mb = Wmg + (size_t)n_blk * IN;

    u64 accW[4][4], accM[4][4];
    #pragma unroll
    for (int j = 0; j < 4; j++)
        #pragma unroll
        for (int i = 0; i < 4; i++) { accW[j][i] = 0ull; accM[j][i] = 0ull; }

    float4 xb[2], wb[2], mb[2];
    #pragma unroll
    for (int r = 0; r < 2; r++) {
        int idx = tid + r * 128;
        int row = idx >> 2, k4 = (idx & 3) << 2;
        size_t off = (size_t)row * IN + k4;
        xb[r] = *(const float4*)(Xb + off);
        wb[r] = *(const float4*)(Wb + off);
        mb[r] = *(const float4*)(Mb + off);
    }

    for (int k0 = 0; k0 < IN; k0 += BK) {
        #pragma unroll
        for (int r = 0; r < 2; r++) {
            int idx = tid + r * 128;
            int row = idx >> 2, k4 = (idx & 3) << 2;
            sX[k4 + 0][row] = xb[r].x; sX[k4 + 1][row] = xb[r].y;
            sX[k4 + 2][row] = xb[r].z; sX[k4 + 3][row] = xb[r].w;
            sW[k4 + 0][row] = wb[r].x; sW[k4 + 1][row] = wb[r].y;
            sW[k4 + 2][row] = wb[r].z; sW[k4 + 3][row] = wb[r].w;
            sM[k4 + 0][row] = mb[r].x; sM[k4 + 1][row] = mb[r].y;
            sM[k4 + 2][row] = mb[r].z; sM[k4 + 3][row] = mb[r].w;
        }
        __syncthreads();

        if (k0 + BK < IN) {
            #pragma unroll
            for (int r = 0; r < 2; r++) {
                int idx = tid + r * 128;
                int row = idx >> 2, k4 = (idx & 3) << 2;
                size_t off = (size_t)row * IN + (k0 + BK) + k4;
                xb[r] = *(const float4*)(Xb + off);
                wb[r] = *(const float4*)(Wb + off);
                mb[r] = *(const float4*)(Mb + off);
            }
        }

        #pragma unroll
        for (int kk = 0; kk < BK; kk++) {
            u64 a[4];
            #pragma unroll
            for (int i = 0; i < 4; i++)
                a[i] = *(const u64*)&sX[kk][ty * 8 + 2 * i];
            #pragma unroll
            for (int j = 0; j < 4; j++) {
                u64 w2 = pack2(sW[kk][tx * 4 + j]);
                u64 m2 = pack2(sM[kk][tx * 4 + j]);
                #pragma unroll
                for (int i = 0; i < 4; i++) {
                    accW[j][i] = fma2(a[i], w2, accW[j][i]);
                    accM[j][i] = fma2(a[i], m2, accM[j][i]);
                }
            }
        }
        __syncthreads();
    }

    float bv[4];
    #pragma unroll
    for (int j = 0; j < 4; j++) bv[j] = bg[n_blk + tx * 4 + j];

    float* P = g_P[g];
    #pragma unroll
    for (int i = 0; i < 4; i++) {
        float2 w[4], mm[4];
        #pragma unroll
        for (int j = 0; j < 4; j++) { w[j] = unpack2(accW[j][i]); mm[j] = unpack2(accM[j][i]); }
        const int m = m_blk + ty * 8 + 2 * i;
        float4 v0, v1;
        v0.x = sigmoidf_(mm[0].x) * w[0].x + bv[0];
        v0.y = sigmoidf_(mm[1].x) * w[1].x + bv[1];
        v0.z = sigmoidf_(mm[2].x) * w[2].x + bv[2];
        v0.w = sigmoidf_(mm[3].x) * w[3].x + bv[3];
        v1.x = sigmoidf_(mm[0].y) * w[0].y + bv[0];
        v1.y = sigmoidf_(mm[1].y) * w[1].y + bv[1];
        v1.z = sigmoidf_(mm[2].y) * w[2].y + bv[2];
        v1.w = sigmoidf_(mm[3].y) * w[3].y + bv[3];
        *(float4*)&P[(size_t)m * H + n_blk + tx * 4]       = v0;
        *(float4*)&P[(size_t)(m + 1) * H + n_blk + tx * 4] = v1;
    }
}

// ---------------------------------------------------------------------------
// Persistent recurrence kernel.
// 128 blocks; block nb owns N-columns [nb*8, nb*8+8). All 6 U matrices for
// this slice live in SMEM (192 KB). c lives in registers. h ping-pongs via
// global buffers + grid barrier.
//
// Thread map (256 threads): tx = tid&7 -> n within slice; tym = tid>>3 -> m
// pair base b0 = tym*2. Each thread owns outputs (b0, n), (b0+1, n) for all
// 6 matrices as 3 f32x2 pairs per row ((Uf,Umf),(Uo,Umo),(Uc,Umc)).
// ---------------------------------------------------------------------------
constexpr int SU_WORDS = 1024 * 48;          // [k][n8][mat6]
constexpr int SH_STRIDE = 66;                // 64 + 2 pad (keeps 8B align, kills conflicts)
constexpr int SH_WORDS = 64 * SH_STRIDE;     // one 64-k chunk of h
constexpr int RSMEM_BYTES = (SU_WORDS + SH_WORDS) * 4;

__global__ __launch_bounds__(RTHREADS, 1)
void lstm_persist(const float* __restrict__ Uf, const float* __restrict__ Umf,
                  const float* __restrict__ Uo, const float* __restrict__ Umo,
                  const float* __restrict__ Uc, const float* __restrict__ Umc,
                  float* __restrict__ out)
{
    extern __shared__ float smem[];
    float* sU = smem;                 // idx = k*48 + n*6 + mat  (mats: f,mf,o,mo,c,mc)
    float* sH = smem + SU_WORDS;      // idx = kk*66 + m

    const int tid = threadIdx.x;
    const int tx  = tid & 7;          // n within slice
    const int tym = tid >> 3;         // 0..31
    const int b0  = tym * 2;
    const int nb  = blockIdx.x * 8;
    const int n   = nb + tx;

    // ---- one-time: load U slice into SMEM (coalesced LDG.128) ----
    {
        const float* Us[6] = {Uf, Umf, Uo, Umo, Uc, Umc};
        #pragma unroll
        for (int mat = 0; mat < 6; mat++) {
            #pragma unroll
            for (int nn = 0; nn < 8; nn++) {
                const float* src = Us[mat] + (size_t)(nb + nn) * H;
                int k4 = tid * 4;     // 256 threads * 4 = 1024 = H
                float4 v = *(const float4*)(src + k4);
                float* dst = sU + (size_t)k4 * 48 + nn * 6 + mat;
                dst[0]      = v.x;
                dst[48]     = v.y;
                dst[96]     = v.z;
                dst[144]    = v.w;
            }
        }
    }

    // ---- zero h0 slice (this block's n-columns, all b) ----
    for (int i = tid; i < B * 8; i += RTHREADS) {
        int bb = i >> 3, nn = nb + (i & 7);
        g_h[0][bb * H + nn] = 0.0f;
    }

    float creg0 = 0.0f, creg1 = 0.0f;
    float hlast0 = 0.0f, hlast1 = 0.0f;

    grid_barrier();   // h0 + all U slices staged

    // staging map: sm = m row (0..63), sk = k sub-offset {0,4,8,12};
    // thread loads k offsets sk + r*16 + {0..3} for r=0..3 (conflict-free STS)
    const int sm = tid >> 2;
    const int sk = (tid & 3) * 4;

    for (int t = 0; t < T; t++) {
        const float* __restrict__ hp = g_h[t & 1];
        float* __restrict__ hn = g_h[(t + 1) & 1];

        u64 acc[6];
        #pragma unroll
        for (int i = 0; i < 6; i++) acc[i] = 0ull;

        // prefetch chunk 0
        const float* hrow = hp + (size_t)sm * H + sk;
        float4 hv[4];
        #pragma unroll
        for (int r = 0; r < 4; r++) hv[r] = ldcg4(hrow + r * 16);

        for (int k0 = 0; k0 < H; k0 += 64) {
            __syncthreads();
            #pragma unroll
            for (int r = 0; r < 4; r++) {
                int kb = sk + r * 16;
                sH[(kb + 0) * SH_STRIDE + sm] = hv[r].x;
                sH[(kb + 1) * SH_STRIDE + sm] = hv[r].y;
                sH[(kb + 2) * SH_STRIDE + sm] = hv[r].z;
                sH[(kb + 3) * SH_STRIDE + sm] = hv[r].w;
            }
            __syncthreads();

            if (k0 + 64 < H) {
                const float* hnext_row = hp + (size_t)sm * H + (k0 + 64) + sk;
                #pragma unroll
                for (int r = 0; r < 4; r++) hv[r] = ldcg4(hnext_row + r * 16);
            }

            const float* wbase = sU + (size_t)k0 * 48 + tx * 6;
            #pragma unroll
            for (int kk = 0; kk < 64; kk++) {
                const float* wrow = wbase + kk * 48;
                u64 w0 = *(const u64*)(wrow + 0);
                u64 w1 = *(const u64*)(wrow + 2);
                u64 w2 = *(const u64*)(wrow + 4);
                float2 h2 = *(const float2*)(sH + kk * SH_STRIDE + b0);
                u64 a0 = pack2(h2.x);
                u64 a1 = pack2(h2.y);
                acc[0] = fma2(a0, w0, acc[0]);
                acc[1] = fma2(a0, w1, acc[1]);
                acc[2] = fma2(a0, w2, acc[2]);
                acc[3] = fma2(a1, w0, acc[3]);
                acc[4] = fma2(a1, w1, acc[4]);
                acc[5] = fma2(a1, w2, acc[5]);
            }
        }

        // ---- fused LSTM cell epilogue (thread-local) ----
        #pragma unroll
        for (int mrow = 0; mrow < 2; mrow++) {
            int bb = b0 + mrow;
            float2 vf = unpack2(acc[mrow * 3 + 0]);  // (Uf·h, Umf·h)
            float2 vo = unpack2(acc[mrow * 3 + 1]);  // (Uo·h, Umo·h)
            float2 vc = unpack2(acc[mrow * 3 + 2]);  // (Uc·h, Umc·h)
            float rf = sigmoidf_(vf.y) * vf.x;
            float ro = sigmoidf_(vo.y) * vo.x;
            float rc = sigmoidf_(vc.y) * vc.x;
            size_t pidx = ((size_t)(bb * T + t)) * H + n;
            float f = sigmoidf_(__ldcs(&g_P[0][pidx]) + rf);
            float o = sigmoidf_(__ldcs(&g_P[1][pidx]) + ro);
            float cprev = mrow ? creg1 : creg0;
            float cn = f * cprev + tanhf(__ldcs(&g_P[2][pidx]) + rc);
            float hval = o * cn;
            if (mrow) { creg1 = cn; hlast1 = hval; } else { creg0 = cn; hlast0 = hval; }
            hn[bb * H + n] = hval;
            out[pidx] = hval;
        }

        grid_barrier();
    }

    // final states: h then c, each [B,H], appended after [B,T,H]
    out[(size_t)M * H + (size_t)b0 * H + n]                 = hlast0;
    out[(size_t)M * H + (size_t)(b0 + 1) * H + n]           = hlast1;
    out[(size_t)M * H + (size_t)B * H + (size_t)b0 * H + n]       = creg0;
    out[(size_t)M * H + (size_t)B * H + (size_t)(b0 + 1) * H + n] = creg1;
}

} // anonymous namespace

extern "C" void kernel_launch(void* const* d_in, const int* in_sizes, int n_in,
                              void* d_out, int out_size) {
    (void)in_sizes; (void)n_in; (void)out_size;
    const float* X    = (const float*)d_in[0];
    const float* W_f  = (const float*)d_in[1];
    const float* Wm_f = (const float*)d_in[2];
    const float* U_f  = (const float*)d_in[3];
    const float* Um_f = (const float*)d_in[4];
    const float* b_f  = (const float*)d_in[5];
    // inputs 6..10 are the i-gate: computed but unused by the reference -> skipped
    const float* W_o  = (const float*)d_in[11];
    const float* Wm_o = (const float*)d_in[12];
    const float* U_o  = (const float*)d_in[13];
    const float* Um_o = (const float*)d_in[14];
    const float* b_o  = (const float*)d_in[15];
    const float* W_c  = (const float*)d_in[16];
    const float* Wm_c = (const float*)d_in[17];
    const float* U_c  = (const float*)d_in[18];
    const float* Um_c = (const float*)d_in[19];
    const float* b_c  = (const float*)d_in[20];
    float* out = (float*)d_out;

    static int smem_set = 0;
    if (!smem_set) {
        cudaFuncSetAttribute(lstm_persist,
                             cudaFuncAttributeMaxDynamicSharedMemorySize,
                             RSMEM_BYTES);
        smem_set = 1;
    }

    dim3 pg(H / BN, M / BM, 3);
    input_proj<<<pg, 128>>>(X, W_f, Wm_f, b_f, W_o, Wm_o, b_o, W_c, Wm_c, b_c);

    lstm_persist<<<RGRID, RTHREADS, RSMEM_BYTES>>>(U_f, Um_f, U_o, Um_o, U_c, Um_c, out);
}

// round 7
// speedup vs baseline: 2.2928x; 1.4526x over previous
#include <cuda_runtime.h>
#include <math.h>

namespace {

constexpr int B  = 64;
constexpr int T  = 256;
constexpr int IN = 512;
constexpr int H  = 1024;
constexpr int M  = B * T;   // 16384

constexpr int RGRID = 128;  // persistent blocks, each owns 8 N-columns
constexpr int RTHREADS = 256;

typedef unsigned long long u64;

// Scratch (device globals — no allocation allowed)
__device__ float g_P[3][(size_t)M * H];   // masked input projections + bias: [f, o, c]
__device__ float g_h[2][H * B];           // h ping-pong, K-MAJOR: [n(H)][b(B)]

// grid barrier state
__device__ unsigned g_bar_count = 0;
__device__ volatile unsigned g_bar_gen = 0;

__device__ __forceinline__ u64 pack2(float v) {
    u64 r; asm("mov.b64 %0, {%1, %2};" : "=l"(r) : "f"(v), "f"(v)); return r;
}
__device__ __forceinline__ u64 pack_pair(float x, float y) {
    u64 r; asm("mov.b64 %0, {%1, %2};" : "=l"(r) : "f"(x), "f"(y)); return r;
}
__device__ __forceinline__ u64 fma2(u64 a, u64 b, u64 c) {
    u64 d; asm("fma.rn.f32x2 %0, %1, %2, %3;" : "=l"(d) : "l"(a), "l"(b), "l"(c)); return d;
}
__device__ __forceinline__ float2 unpack2(u64 v) {
    float2 f; asm("mov.b64 {%0, %1}, %2;" : "=f"(f.x), "=f"(f.y) : "l"(v)); return f;
}
__device__ __forceinline__ float sigmoidf_(float x) { return 1.0f / (1.0f + expf(-x)); }

__device__ __forceinline__ float4 ldcg4(const float* p) {
    float4 v;
    asm volatile("ld.global.cg.v4.f32 {%0,%1,%2,%3}, [%4];"
                 : "=f"(v.x), "=f"(v.y), "=f"(v.z), "=f"(v.w) : "l"(p));
    return v;
}

// All blocks are co-resident (1 block/SM via smem footprint, grid 128 <= 148 SMs).
__device__ __forceinline__ void grid_barrier() {
    __syncthreads();
    if (threadIdx.x == 0) {
        __threadfence();
        unsigned old = g_bar_gen;
        if (atomicAdd(&g_bar_count, 1u) == (unsigned)(gridDim.x - 1)) {
            g_bar_count = 0;
            __threadfence();
            g_bar_gen = old + 1;
        } else {
            while (g_bar_gen == old) { }
        }
        __threadfence();
    }
    __syncthreads();
}

// ---------------------------------------------------------------------------
// Input projection: P_g[m][n] = sigmoid(X[m]·Wm_g[n]) * (X[m]·W_g[n]) + b_g[n]
// GEMM M=16384, N=1024, K=512, two B-matrices per output. (unchanged)
// ---------------------------------------------------------------------------
constexpr int BM = 64, BN = 64, BK = 16;

__global__ __launch_bounds__(128)
void input_proj(const float* __restrict__ X,
                const float* __restrict__ W0, const float* __restrict__ Wm0, const float* __restrict__ b0,
                const float* __restrict__ W1, const float* __restrict__ Wm1, const float* __restrict__ b1,
                const float* __restrict__ W2, const float* __restrict__ Wm2, const float* __restrict__ b2)
{
    __shared__ __align__(16) float sX[BK][BM + 2];
    __shared__ __align__(16) float sW[BK][BN + 2];
    __shared__ __align__(16) float sM[BK][BN + 2];

    const int g = blockIdx.z;
    const float* Wg  = (g == 0) ? W0  : (g == 1) ? W1  : W2;
    const float* Wmg = (g == 0) ? Wm0 : (g == 1) ? Wm1 : Wm2;
    const float* bg  = (g == 0) ? b0  : (g == 1) ? b1  : b2;

    const int tid = threadIdx.x;
    const int tx = tid & 15;
    const int ty = tid >> 4;
    const int m_blk = blockIdx.y * BM;
    const int n_blk = blockIdx.x * BN;

    const float* Xb = X   + (size_t)m_blk * IN;
    const float* Wb = Wg  + (size_t)n_blk * IN;
    const float* Mb = Wmg + (size_t)n_blk * IN;

    u64 accW[4][4], accM[4][4];
    #pragma unroll
    for (int j = 0; j < 4; j++)
        #pragma unroll
        for (int i = 0; i < 4; i++) { accW[j][i] = 0ull; accM[j][i] = 0ull; }

    float4 xb[2], wb[2], mb[2];
    #pragma unroll
    for (int r = 0; r < 2; r++) {
        int idx = tid + r * 128;
        int row = idx >> 2, k4 = (idx & 3) << 2;
        size_t off = (size_t)row * IN + k4;
        xb[r] = *(const float4*)(Xb + off);
        wb[r] = *(const float4*)(Wb + off);
        mb[r] = *(const float4*)(Mb + off);
    }

    for (int k0 = 0; k0 < IN; k0 += BK) {
        #pragma unroll
        for (int r = 0; r < 2; r++) {
            int idx = tid + r * 128;
            int row = idx >> 2, k4 = (idx & 3) << 2;
            sX[k4 + 0][row] = xb[r].x; sX[k4 + 1][row] = xb[r].y;
            sX[k4 + 2][row] = xb[r].z; sX[k4 + 3][row] = xb[r].w;
            sW[k4 + 0][row] = wb[r].x; sW[k4 + 1][row] = wb[r].y;
            sW[k4 + 2][row] = wb[r].z; sW[k4 + 3][row] = wb[r].w;
            sM[k4 + 0][row] = mb[r].x; sM[k4 + 1][row] = mb[r].y;
            sM[k4 + 2][row] = mb[r].z; sM[k4 + 3][row] = mb[r].w;
        }
        __syncthreads();

        if (k0 + BK < IN) {
            #pragma unroll
            for (int r = 0; r < 2; r++) {
                int idx = tid + r * 128;
                int row = idx >> 2, k4 = (idx & 3) << 2;
                size_t off = (size_t)row * IN + (k0 + BK) + k4;
                xb[r] = *(const float4*)(Xb + off);
                wb[r] = *(const float4*)(Wb + off);
                mb[r] = *(const float4*)(Mb + off);
            }
        }

        #pragma unroll
        for (int kk = 0; kk < BK; kk++) {
            u64 a[4];
            #pragma unroll
            for (int i = 0; i < 4; i++)
                a[i] = *(const u64*)&sX[kk][ty * 8 + 2 * i];
            #pragma unroll
            for (int j = 0; j < 4; j++) {
                u64 w2 = pack2(sW[kk][tx * 4 + j]);
                u64 m2 = pack2(sM[kk][tx * 4 + j]);
                #pragma unroll
                for (int i = 0; i < 4; i++) {
                    accW[j][i] = fma2(a[i], w2, accW[j][i]);
                    accM[j][i] = fma2(a[i], m2, accM[j][i]);
                }
            }
        }
        __syncthreads();
    }

    float bv[4];
    #pragma unroll
    for (int j = 0; j < 4; j++) bv[j] = bg[n_blk + tx * 4 + j];

    float* P = g_P[g];
    #pragma unroll
    for (int i = 0; i < 4; i++) {
        float2 w[4], mm[4];
        #pragma unroll
        for (int j = 0; j < 4; j++) { w[j] = unpack2(accW[j][i]); mm[j] = unpack2(accM[j][i]); }
        const int m = m_blk + ty * 8 + 2 * i;
        float4 v0, v1;
        v0.x = sigmoidf_(mm[0].x) * w[0].x + bv[0];
        v0.y = sigmoidf_(mm[1].x) * w[1].x + bv[1];
        v0.z = sigmoidf_(mm[2].x) * w[2].x + bv[2];
        v0.w = sigmoidf_(mm[3].x) * w[3].x + bv[3];
        v1.x = sigmoidf_(mm[0].y) * w[0].y + bv[0];
        v1.y = sigmoidf_(mm[1].y) * w[1].y + bv[1];
        v1.z = sigmoidf_(mm[2].y) * w[2].y + bv[2];
        v1.w = sigmoidf_(mm[3].y) * w[3].y + bv[3];
        *(float4*)&P[(size_t)m * H + n_blk + tx * 4]       = v0;
        *(float4*)&P[(size_t)(m + 1) * H + n_blk + tx * 4] = v1;
    }
}

// ---------------------------------------------------------------------------
// Persistent recurrence kernel (v2).
// 128 blocks; block owns 8 N-columns; 6 U matrices for the slice in SMEM.
// Thread map (256 thr): tx = tid&7 (n), tb = (tid>>3)&7 (8 b-rows, b0=tb*8),
// kz = tid>>6 (k-split 4). Per thread: 24 u64 accs = 8 b x 3 (U,Um)-pairs.
// h ping-pong buffers are K-MAJOR [n][b]: staging is a straight copy.
// ---------------------------------------------------------------------------
constexpr int SU_WORDS = 1024 * 48;         // [k][n8][mat6]
constexpr int SH_WORDS = 4 * 32 * 64;       // [kz][kk32][b64] = 8192 words (32KB)
constexpr int RSMEM_BYTES = (SU_WORDS + SH_WORDS) * 4;   // 229376 B

__global__ __launch_bounds__(RTHREADS, 1)
void lstm_persist(const float* __restrict__ Uf, const float* __restrict__ Umf,
                  const float* __restrict__ Uo, const float* __restrict__ Umo,
                  const float* __restrict__ Uc, const float* __restrict__ Umc,
                  float* __restrict__ out)
{
    extern __shared__ float smem[];
    float* sU = smem;                 // idx = k*48 + n*6 + mat  (f,mf,o,mo,c,mc)
    float* sH = smem + SU_WORDS;      // idx = (kz*32 + kk)*64 + b

    const int tid = threadIdx.x;
    const int tx  = tid & 7;          // n within slice
    const int tb  = (tid >> 3) & 7;   // b-group
    const int kz  = tid >> 6;         // k partition 0..3
    const int b0  = tb * 8;
    const int nb  = blockIdx.x * 8;
    const int n   = nb + tx;

    // ---- one-time: load U slice into SMEM ----
    {
        const float* Us[6] = {Uf, Umf, Uo, Umo, Uc, Umc};
        #pragma unroll
        for (int mat = 0; mat < 6; mat++) {
            #pragma unroll
            for (int nn = 0; nn < 8; nn++) {
                const float* src = Us[mat] + (size_t)(nb + nn) * H;
                int k4 = tid * 4;
                float4 v = *(const float4*)(src + k4);
                float* dst = sU + (size_t)k4 * 48 + nn * 6 + mat;
                dst[0]   = v.x;
                dst[48]  = v.y;
                dst[96]  = v.z;
                dst[144] = v.w;
            }
        }
    }

    // ---- zero h0 slice ([n][b] layout, this block's 8 n-rows) ----
    for (int i = tid; i < 8 * B; i += RTHREADS)
        g_h[0][(size_t)(nb + (i >> 6)) * B + (i & 63)] = 0.0f;

    float creg[8], hlast[8];
    #pragma unroll
    for (int j = 0; j < 8; j++) { creg[j] = 0.0f; hlast[j] = 0.0f; }

    grid_barrier();   // h0 + all U slices staged

    for (int t = 0; t < T; t++) {
        const float* __restrict__ hp = g_h[t & 1];
        float* __restrict__ hn = g_h[(t + 1) & 1];

        u64 acc[8][3];
        #pragma unroll
        for (int j = 0; j < 8; j++)
            #pragma unroll
            for (int mp = 0; mp < 3; mp++) acc[j][mp] = 0ull;

        // prefetch round 0 (each round = 32 k per partition, 8KB x 4)
        float4 pf[8];
        #pragma unroll
        for (int j = 0; j < 8; j++) {
            int fid = tid + j * 256;
            int row = fid >> 4;               // 0..127 = kz*32+kk
            int b4  = (fid & 15) * 4;
            int kzl = row >> 5, kkl = row & 31;
            pf[j] = ldcg4(hp + (size_t)(kzl * 256 + kkl) * B + b4);
        }

        for (int r = 0; r < 8; r++) {
            __syncthreads();
            #pragma unroll
            for (int j = 0; j < 8; j++) {
                int fid = tid + j * 256;
                int row = fid >> 4;
                int b4  = (fid & 15) * 4;
                *(float4*)(sH + (size_t)row * 64 + b4) = pf[j];
            }
            __syncthreads();

            if (r < 7) {
                #pragma unroll
                for (int j = 0; j < 8; j++) {
                    int fid = tid + j * 256;
                    int row = fid >> 4;
                    int b4  = (fid & 15) * 4;
                    int kzl = row >> 5, kkl = row & 31;
                    pf[j] = ldcg4(hp + (size_t)(kzl * 256 + (r + 1) * 32 + kkl) * B + b4);
                }
            }

            const float* wrow = sU + (size_t)(kz * 256 + r * 32) * 48 + tx * 6;
            const float* hrow = sH + (size_t)kz * 32 * 64 + b0;
            #pragma unroll 8
            for (int kk = 0; kk < 32; kk++) {
                u64 w0 = *(const u64*)(wrow + 0);
                u64 w1 = *(const u64*)(wrow + 2);
                u64 w2 = *(const u64*)(wrow + 4);
                float4 ha = *(const float4*)(hrow);
                float4 hb = *(const float4*)(hrow + 4);
                u64 a0 = pack2(ha.x), a1 = pack2(ha.y), a2 = pack2(ha.z), a3 = pack2(ha.w);
                u64 a4 = pack2(hb.x), a5 = pack2(hb.y), a6 = pack2(hb.z), a7 = pack2(hb.w);
                acc[0][0] = fma2(a0, w0, acc[0][0]); acc[0][1] = fma2(a0, w1, acc[0][1]); acc[0][2] = fma2(a0, w2, acc[0][2]);
                acc[1][0] = fma2(a1, w0, acc[1][0]); acc[1][1] = fma2(a1, w1, acc[1][1]); acc[1][2] = fma2(a1, w2, acc[1][2]);
                acc[2][0] = fma2(a2, w0, acc[2][0]); acc[2][1] = fma2(a2, w1, acc[2][1]); acc[2][2] = fma2(a2, w2, acc[2][2]);
                acc[3][0] = fma2(a3, w0, acc[3][0]); acc[3][1] = fma2(a3, w1, acc[3][1]); acc[3][2] = fma2(a3, w2, acc[3][2]);
                acc[4][0] = fma2(a4, w0, acc[4][0]); acc[4][1] = fma2(a4, w1, acc[4][1]); acc[4][2] = fma2(a4, w2, acc[4][2]);
                acc[5][0] = fma2(a5, w0, acc[5][0]); acc[5][1] = fma2(a5, w1, acc[5][1]); acc[5][2] = fma2(a5, w2, acc[5][2]);
                acc[6][0] = fma2(a6, w0, acc[6][0]); acc[6][1] = fma2(a6, w1, acc[6][1]); acc[6][2] = fma2(a6, w2, acc[6][2]);
                acc[7][0] = fma2(a7, w0, acc[7][0]); acc[7][1] = fma2(a7, w1, acc[7][1]); acc[7][2] = fma2(a7, w2, acc[7][2]);
                wrow += 48;
                hrow += 64;
            }
        }

        // ---- prefetch g_P for the epilogue (kz==0 only) while reducing ----
        float pfP[3][8];
        if (kz == 0) {
            #pragma unroll
            for (int j = 0; j < 8; j++) {
                size_t pidx = ((size_t)((b0 + j) * T + t)) * H + n;
                pfP[0][j] = __ldcs(&g_P[0][pidx]);
                pfP[1][j] = __ldcs(&g_P[1][pidx]);
                pfP[2][j] = __ldcs(&g_P[2][pidx]);
            }
        }

        // ---- k-split reduction (sH reused as float2 buffer) ----
        float2* rbuf = (float2*)sH;          // capacity 4096 float2; we use 2*1536
        const int cell = tid & 63;           // (tb, tx) cell id
        __syncthreads();
        if (kz == 1 || kz == 3) {
            float2* dst = rbuf + (kz >> 1) * 1536;
            #pragma unroll
            for (int j = 0; j < 8; j++)
                #pragma unroll
                for (int mp = 0; mp < 3; mp++)
                    dst[(j * 3 + mp) * 64 + cell] = unpack2(acc[j][mp]);
        }
        __syncthreads();
        if (kz == 0 || kz == 2) {
            const float2* src = rbuf + (kz >> 1) * 1536;
            #pragma unroll
            for (int j = 0; j < 8; j++)
                #pragma unroll
                for (int mp = 0; mp < 3; mp++) {
                    float2 s = src[(j * 3 + mp) * 64 + cell];
                    float2 v = unpack2(acc[j][mp]);
                    acc[j][mp] = pack_pair(v.x + s.x, v.y + s.y);
                }
        }
        __syncthreads();
        if (kz == 2) {
            #pragma unroll
            for (int j = 0; j < 8; j++)
                #pragma unroll
                for (int mp = 0; mp < 3; mp++)
                    rbuf[(j * 3 + mp) * 64 + cell] = unpack2(acc[j][mp]);
        }
        __syncthreads();

        // ---- fused LSTM cell epilogue (kz==0 threads own the cells) ----
        if (kz == 0) {
            #pragma unroll
            for (int j = 0; j < 8; j++) {
                int bb = b0 + j;
                float2 vf = unpack2(acc[j][0]);
                float2 vo = unpack2(acc[j][1]);
                float2 vc = unpack2(acc[j][2]);
                float2 sf = rbuf[(j * 3 + 0) * 64 + cell];
                float2 so = rbuf[(j * 3 + 1) * 64 + cell];
                float2 sc = rbuf[(j * 3 + 2) * 64 + cell];
                vf.x += sf.x; vf.y += sf.y;
                vo.x += so.x; vo.y += so.y;
                vc.x += sc.x; vc.y += sc.y;
                float rf = sigmoidf_(vf.y) * vf.x;
                float ro = sigmoidf_(vo.y) * vo.x;
                float rc = sigmoidf_(vc.y) * vc.x;
                float f = sigmoidf_(pfP[0][j] + rf);
                float o = sigmoidf_(pfP[1][j] + ro);
                float cn = f * creg[j] + tanhf(pfP[2][j] + rc);
                creg[j] = cn;
                float hval = o * cn;
                hlast[j] = hval;
                hn[(size_t)n * B + bb] = hval;                       // K-major h
                out[((size_t)(bb * T + t)) * H + n] = hval;
            }
        }

        grid_barrier();
    }

    // final states: h then c, each [B,H], appended after [B,T,H]
    if (kz == 0) {
        #pragma unroll
        for (int j = 0; j < 8; j++) {
            int bb = b0 + j;
            out[(size_t)M * H + (size_t)bb * H + n]               = hlast[j];
            out[(size_t)M * H + (size_t)B * H + (size_t)bb * H + n] = creg[j];
        }
    }
}

} // anonymous namespace

extern "C" void kernel_launch(void* const* d_in, const int* in_sizes, int n_in,
                              void* d_out, int out_size) {
    (void)in_sizes; (void)n_in; (void)out_size;
    const float* X    = (const float*)d_in[0];
    const float* W_f  = (const float*)d_in[1];
    const float* Wm_f = (const float*)d_in[2];
    const float* U_f  = (const float*)d_in[3];
    const float* Um_f = (const float*)d_in[4];
    const float* b_f  = (const float*)d_in[5];
    // inputs 6..10 (i-gate) are computed but unused by the reference -> skipped
    const float* W_o  = (const float*)d_in[11];
    const float* Wm_o = (const float*)d_in[12];
    const float* U_o  = (const float*)d_in[13];
    const float* Um_o = (const float*)d_in[14];
    const float* b_o  = (const float*)d_in[15];
    const float* W_c  = (const float*)d_in[16];
    const float* Wm_c = (const float*)d_in[17];
    const float* U_c  = (const float*)d_in[18];
    const float* Um_c = (const float*)d_in[19];
    const float* b_c  = (const float*)d_in[20];
    float* out = (float*)d_out;

    static int smem_set = 0;
    if (!smem_set) {
        cudaFuncSetAttribute(lstm_persist,
                             cudaFuncAttributeMaxDynamicSharedMemorySize,
                             RSMEM_BYTES);
        smem_set = 1;
    }

    dim3 pg(H / BN, M / BM, 3);
    input_proj<<<pg, 128>>>(X, W_f, Wm_f, b_f, W_o, Wm_o, b_o, W_c, Wm_c, b_c);

    lstm_persist<<<RGRID, RTHREADS, RSMEM_BYTES>>>(U_f, Um_f, U_o, Um_o, U_c, Um_c, out);
}